// round 3
// baseline (speedup 1.0000x reference)
#include <cuda_runtime.h>
#include <cstdint>

#define N_TOTAL 100000
#define DIM     128
#define N_USER  50000
#define M_ENT   50000
#define E_MAX   1700000           // total edges both entities (spec: 1.6M)
#define GEMM_BLOCKS_PER_ENT 391   // ceil(50000/128)

// Scratch (device globals; no dynamic allocation allowed)
__device__ float g_li[(size_t)N_TOTAL * DIM];     // SpMM result, 51.2 MB
__device__ int   g_cnt[N_TOTAL];                  // row degrees
__device__ int   g_off[N_TOTAL];                  // row start offsets (exclusive scan)
__device__ int   g_cur[N_TOTAL];                  // running cursors for permutation
__device__ int   g_cols_s[E_MAX];                 // cols reordered by destination row
__device__ float g_vals_s[E_MAX];                 // vals reordered by destination row

// ---------------------------------------------------------------------------
// 0) zero the degree counters
// ---------------------------------------------------------------------------
__global__ void zero_cnt_kernel() {
    int i = blockIdx.x * blockDim.x + threadIdx.x;
    if (i < N_TOTAL) g_cnt[i] = 0;
}

// ---------------------------------------------------------------------------
// 1) histogram of destination rows (both entities, one launch)
// ---------------------------------------------------------------------------
__global__ void hist_kernel(const int* __restrict__ rows_u,
                            const int* __restrict__ rows_i,
                            int E_u, int E_i) {
    int e = blockIdx.x * blockDim.x + threadIdx.x;
    if (e < E_u) {
        atomicAdd(&g_cnt[__ldg(rows_u + e)], 1);
    } else {
        e -= E_u;
        if (e < E_i) atomicAdd(&g_cnt[N_USER + __ldg(rows_i + e)], 1);
    }
}

// ---------------------------------------------------------------------------
// 2) exclusive scan of g_cnt -> g_off (and g_cur = g_off). One block.
// ---------------------------------------------------------------------------
#define SCAN_THREADS 1024
#define SCAN_CHUNK   98            // 1024*98 = 100352 >= 100000
__global__ void scan_kernel() {
    __shared__ int sums[SCAN_THREADS];
    int t = threadIdx.x;
    int lo = t * SCAN_CHUNK;
    int hi = min(lo + SCAN_CHUNK, N_TOTAL);

    int s = 0;
    for (int i = lo; i < hi; i++) s += g_cnt[i];
    sums[t] = s;
    __syncthreads();

    // Hillis-Steele inclusive scan over per-thread sums
    for (int d = 1; d < SCAN_THREADS; d <<= 1) {
        int v = (t >= d) ? sums[t - d] : 0;
        __syncthreads();
        sums[t] += v;
        __syncthreads();
    }
    int run = (t == 0) ? 0 : sums[t - 1];   // exclusive prefix for this chunk

    for (int i = lo; i < hi; i++) {
        g_off[i] = run;
        g_cur[i] = run;
        run += g_cnt[i];
    }
}

// ---------------------------------------------------------------------------
// 3) permute (col, val) into row-sorted order
// ---------------------------------------------------------------------------
__global__ void permute_kernel(const int*   __restrict__ rows_u,
                               const int*   __restrict__ cols_u,
                               const float* __restrict__ vals_u,
                               const int*   __restrict__ rows_i,
                               const int*   __restrict__ cols_i,
                               const float* __restrict__ vals_i,
                               int E_u, int E_i) {
    int e = blockIdx.x * blockDim.x + threadIdx.x;
    int r, c; float v;
    if (e < E_u) {
        r = __ldg(rows_u + e);
        c = __ldg(cols_u + e);
        v = __ldg(vals_u + e);
    } else {
        e -= E_u;
        if (e >= E_i) return;
        r = N_USER + __ldg(rows_i + e);
        c = __ldg(cols_i + e);
        v = __ldg(vals_i + e);
    }
    int pos = atomicAdd(&g_cur[r], 1);
    g_cols_s[pos] = c;
    g_vals_s[pos] = v;
}

// ---------------------------------------------------------------------------
// 4) gather-form SpMM: one warp per destination row, register accumulation,
//    single plain store. No atomics, no zero-init of g_li needed.
// ---------------------------------------------------------------------------
__global__ __launch_bounds__(256)
void spmm_kernel(const float* __restrict__ ebs) {
    int gwid = (blockIdx.x * blockDim.x + threadIdx.x) >> 5;
    int lane = threadIdx.x & 31;
    if (gwid >= N_TOTAL) return;

    int start = g_off[gwid];
    int cnt   = g_cnt[gwid];

    float4 acc = make_float4(0.f, 0.f, 0.f, 0.f);

    for (int base = 0; base < cnt; base += 32) {
        int idx = base + lane;
        int c = 0; float v = 0.f;
        if (idx < cnt) {             // coalesced edge-list load
            c = __ldg(g_cols_s + start + idx);
            v = __ldg(g_vals_s + start + idx);
        }
        int m = cnt - base;          // edges in this batch (may exceed 32; clamp below)
#pragma unroll
        for (int j = 0; j < 32; j++) {
            int   cj = __shfl_sync(0xffffffffu, c, j);
            float vj = __shfl_sync(0xffffffffu, v, j);
            if (j < m) {
                float4 e = *reinterpret_cast<const float4*>(
                    ebs + (size_t)cj * DIM + lane * 4);
                acc.x = fmaf(vj, e.x, acc.x);
                acc.y = fmaf(vj, e.y, acc.y);
                acc.z = fmaf(vj, e.z, acc.z);
                acc.w = fmaf(vj, e.w, acc.w);
            }
        }
    }
    *reinterpret_cast<float4*>(g_li + (size_t)gwid * DIM + lane * 4) = acc;
}

// ---------------------------------------------------------------------------
// 5) Fused GEMM+ReLU for both entities (unchanged from R2).
// ---------------------------------------------------------------------------
__global__ __launch_bounds__(256, 2)
void gemm_relu_kernel(const float* __restrict__ Wu,
                      const float* __restrict__ Wi,
                      float*       __restrict__ out) {
    __shared__ float As[2][8][128];
    __shared__ float Ws[2][8][128];

    int b = blockIdx.x;
    int entity = (b >= GEMM_BLOCKS_PER_ENT) ? 1 : 0;
    const float* W = entity ? Wi : Wu;
    int rowBase = (b - entity * GEMM_BLOCKS_PER_ENT) * 128;
    const float* A = g_li + (size_t)(entity ? N_USER : 0) * DIM;
    float* O = out + (size_t)(entity ? N_USER : 0) * DIM;

    int tid = threadIdx.x;
    int arow = tid >> 1;
    int akq  = (tid & 1) * 4;
    int agrow = rowBase + arow;
    bool avalid = (agrow < M_ENT);
    const float* aptr = A + (size_t)agrow * DIM + akq;
    int wk = tid >> 5;
    int wc = (tid & 31) * 4;
    const float* wptr = W + (size_t)wk * DIM + wc;

    int tx = tid & 15;
    int ty = tid >> 4;

    float acc[8][8];
#pragma unroll
    for (int i = 0; i < 8; i++)
#pragma unroll
        for (int j = 0; j < 8; j++) acc[i][j] = 0.f;

    {
        float4 a = avalid ? *reinterpret_cast<const float4*>(aptr)
                          : make_float4(0.f, 0.f, 0.f, 0.f);
        As[0][akq + 0][arow] = a.x;
        As[0][akq + 1][arow] = a.y;
        As[0][akq + 2][arow] = a.z;
        As[0][akq + 3][arow] = a.w;
        float4 w = *reinterpret_cast<const float4*>(wptr);
        *reinterpret_cast<float4*>(&Ws[0][wk][wc]) = w;
    }
    __syncthreads();

    int buf = 0;
#pragma unroll
    for (int t = 0; t < 16; t++) {
        if (t < 15) {
            int kk = (t + 1) * 8;
            float4 a = avalid ? *reinterpret_cast<const float4*>(aptr + kk)
                              : make_float4(0.f, 0.f, 0.f, 0.f);
            float4 w = *reinterpret_cast<const float4*>(wptr + (size_t)kk * DIM);
            int nb = buf ^ 1;
            As[nb][akq + 0][arow] = a.x;
            As[nb][akq + 1][arow] = a.y;
            As[nb][akq + 2][arow] = a.z;
            As[nb][akq + 3][arow] = a.w;
            *reinterpret_cast<float4*>(&Ws[nb][wk][wc]) = w;
        }

#pragma unroll
        for (int k = 0; k < 8; k++) {
            float4 a0 = *reinterpret_cast<const float4*>(&As[buf][k][ty * 8]);
            float4 a1 = *reinterpret_cast<const float4*>(&As[buf][k][ty * 8 + 4]);
            float4 w0 = *reinterpret_cast<const float4*>(&Ws[buf][k][tx * 8]);
            float4 w1 = *reinterpret_cast<const float4*>(&Ws[buf][k][tx * 8 + 4]);
            float av[8] = {a0.x, a0.y, a0.z, a0.w, a1.x, a1.y, a1.z, a1.w};
            float wv[8] = {w0.x, w0.y, w0.z, w0.w, w1.x, w1.y, w1.z, w1.w};
#pragma unroll
            for (int i = 0; i < 8; i++)
#pragma unroll
                for (int j = 0; j < 8; j++)
                    acc[i][j] = fmaf(av[i], wv[j], acc[i][j]);
        }
        __syncthreads();
        buf ^= 1;
    }

#pragma unroll
    for (int i = 0; i < 8; i++) {
        int row = rowBase + ty * 8 + i;
        if (row < M_ENT) {
            float4 o0, o1;
            o0.x = fmaxf(acc[i][0], 0.f);
            o0.y = fmaxf(acc[i][1], 0.f);
            o0.z = fmaxf(acc[i][2], 0.f);
            o0.w = fmaxf(acc[i][3], 0.f);
            o1.x = fmaxf(acc[i][4], 0.f);
            o1.y = fmaxf(acc[i][5], 0.f);
            o1.z = fmaxf(acc[i][6], 0.f);
            o1.w = fmaxf(acc[i][7], 0.f);
            *reinterpret_cast<float4*>(O + (size_t)row * DIM + tx * 8)     = o0;
            *reinterpret_cast<float4*>(O + (size_t)row * DIM + tx * 8 + 4) = o1;
        }
    }
}

// ---------------------------------------------------------------------------
extern "C" void kernel_launch(void* const* d_in, const int* in_sizes, int n_in,
                              void* d_out, int out_size) {
    const float* ebs    = (const float*)d_in[0];
    const int*   rows_u = (const int*)  d_in[1];
    const int*   cols_u = (const int*)  d_in[2];
    const float* vals_u = (const float*)d_in[3];
    const float* W_u    = (const float*)d_in[4];
    const int*   rows_i = (const int*)  d_in[5];
    const int*   cols_i = (const int*)  d_in[6];
    const float* vals_i = (const float*)d_in[7];
    const float* W_i    = (const float*)d_in[8];
    float* out = (float*)d_out;

    int E_u = in_sizes[1];
    int E_i = in_sizes[5];
    int E_total = E_u + E_i;

    // 0) zero degree counters
    zero_cnt_kernel<<<(N_TOTAL + 255) / 256, 256>>>();

    // 1) histogram
    hist_kernel<<<(E_total + 255) / 256, 256>>>(rows_u, rows_i, E_u, E_i);

    // 2) exclusive scan -> offsets + cursors
    scan_kernel<<<1, SCAN_THREADS>>>();

    // 3) permute (col, val) by destination row
    permute_kernel<<<(E_total + 255) / 256, 256>>>(rows_u, cols_u, vals_u,
                                                   rows_i, cols_i, vals_i,
                                                   E_u, E_i);

    // 4) gather SpMM (one warp per row)
    {
        int warps = N_TOTAL;
        int blocks = (warps * 32 + 255) / 256;
        spmm_kernel<<<blocks, 256>>>(ebs);
    }

    // 5) fused GEMM + ReLU
    gemm_relu_kernel<<<2 * GEMM_BLOCKS_PER_ENT, 256>>>(W_u, W_i, out);
}

// round 4
// speedup vs baseline: 1.0474x; 1.0474x over previous
#include <cuda_runtime.h>
#include <cstdint>

#define N_TOTAL 100000
#define DIM     128
#define N_USER  50000
#define M_ENT   50000
#define E_MAX   1700000
#define GEMM_BLOCKS_PER_ENT 391   // ceil(50000/128)

// Scratch (device globals; no dynamic allocation allowed)
__device__ float g_li[(size_t)N_TOTAL * DIM];   // SpMM result, 51.2 MB
__device__ int   g_cnt[N_TOTAL];                // row degrees
__device__ int   g_off[N_TOTAL];                // row start offsets
__device__ int   g_cur[N_TOTAL];                // running cursors
__device__ int2  g_edge[E_MAX];                 // packed (col, val) sorted by dest row

// ---------------------------------------------------------------------------
// 0) zero degree counters
// ---------------------------------------------------------------------------
__global__ void zero_cnt_kernel() {
    int i = blockIdx.x * blockDim.x + threadIdx.x;
    if (i < N_TOTAL) g_cnt[i] = 0;
}

// ---------------------------------------------------------------------------
// 1) histogram of destination rows
// ---------------------------------------------------------------------------
__global__ void hist_kernel(const int* __restrict__ rows_u,
                            const int* __restrict__ rows_i,
                            int E_u, int E_i) {
    int e = blockIdx.x * blockDim.x + threadIdx.x;
    if (e < E_u) {
        atomicAdd(&g_cnt[__ldg(rows_u + e)], 1);
    } else {
        e -= E_u;
        if (e < E_i) atomicAdd(&g_cnt[N_USER + __ldg(rows_i + e)], 1);
    }
}

// ---------------------------------------------------------------------------
// 2) exclusive scan (one block)
// ---------------------------------------------------------------------------
#define SCAN_THREADS 1024
#define SCAN_CHUNK   98
__global__ void scan_kernel() {
    __shared__ int sums[SCAN_THREADS];
    int t = threadIdx.x;
    int lo = t * SCAN_CHUNK;
    int hi = min(lo + SCAN_CHUNK, N_TOTAL);

    int s = 0;
    for (int i = lo; i < hi; i++) s += g_cnt[i];
    sums[t] = s;
    __syncthreads();

    for (int d = 1; d < SCAN_THREADS; d <<= 1) {
        int v = (t >= d) ? sums[t - d] : 0;
        __syncthreads();
        sums[t] += v;
        __syncthreads();
    }
    int run = (t == 0) ? 0 : sums[t - 1];

    for (int i = lo; i < hi; i++) {
        g_off[i] = run;
        g_cur[i] = run;
        run += g_cnt[i];
    }
}

// ---------------------------------------------------------------------------
// 3) permute edges into row-sorted order; single STG.64 per edge
// ---------------------------------------------------------------------------
__global__ void permute_kernel(const int*   __restrict__ rows_u,
                               const int*   __restrict__ cols_u,
                               const float* __restrict__ vals_u,
                               const int*   __restrict__ rows_i,
                               const int*   __restrict__ cols_i,
                               const float* __restrict__ vals_i,
                               int E_u, int E_i) {
    int e = blockIdx.x * blockDim.x + threadIdx.x;
    int r, c; float v;
    if (e < E_u) {
        r = __ldg(rows_u + e);
        c = __ldg(cols_u + e);
        v = __ldg(vals_u + e);
    } else {
        e -= E_u;
        if (e >= E_i) return;
        r = N_USER + __ldg(rows_i + e);
        c = __ldg(cols_i + e);
        v = __ldg(vals_i + e);
    }
    int pos = atomicAdd(&g_cur[r], 1);
    g_edge[pos] = make_int2(c, __float_as_int(v));
}

// ---------------------------------------------------------------------------
// 4) gather SpMM: one warp per row; edges staged in smem; unroll x8.
//    Each lane accumulates 4 dims (float4). No atomics, no zero-init.
// ---------------------------------------------------------------------------
__global__ __launch_bounds__(256)
void spmm_kernel(const float* __restrict__ ebs) {
    __shared__ int2 sedge[8][32];

    int wid  = threadIdx.x >> 5;
    int lane = threadIdx.x & 31;
    int row  = blockIdx.x * 8 + wid;
    if (row >= N_TOTAL) return;

    int start = g_off[row];
    int cnt   = g_cnt[row];

    const float4* ebs4 = reinterpret_cast<const float4*>(ebs);
    float4 acc = make_float4(0.f, 0.f, 0.f, 0.f);

    for (int base = 0; base < cnt; base += 32) {
        int m = min(cnt - base, 32);
        if (lane < m)
            sedge[wid][lane] = __ldg(g_edge + start + base + lane);
        __syncwarp();

        int j = 0;
        for (; j + 8 <= m; j += 8) {
            int2 e0 = sedge[wid][j + 0];
            int2 e1 = sedge[wid][j + 1];
            int2 e2 = sedge[wid][j + 2];
            int2 e3 = sedge[wid][j + 3];
            int2 e4 = sedge[wid][j + 4];
            int2 e5 = sedge[wid][j + 5];
            int2 e6 = sedge[wid][j + 6];
            int2 e7 = sedge[wid][j + 7];
            float4 v0 = ebs4[(size_t)e0.x * 32 + lane];
            float4 v1 = ebs4[(size_t)e1.x * 32 + lane];
            float4 v2 = ebs4[(size_t)e2.x * 32 + lane];
            float4 v3 = ebs4[(size_t)e3.x * 32 + lane];
            float4 v4 = ebs4[(size_t)e4.x * 32 + lane];
            float4 v5 = ebs4[(size_t)e5.x * 32 + lane];
            float4 v6 = ebs4[(size_t)e6.x * 32 + lane];
            float4 v7 = ebs4[(size_t)e7.x * 32 + lane];
            float f0 = __int_as_float(e0.y), f1 = __int_as_float(e1.y);
            float f2 = __int_as_float(e2.y), f3 = __int_as_float(e3.y);
            float f4 = __int_as_float(e4.y), f5 = __int_as_float(e5.y);
            float f6 = __int_as_float(e6.y), f7 = __int_as_float(e7.y);
            acc.x = fmaf(f0, v0.x, acc.x); acc.y = fmaf(f0, v0.y, acc.y);
            acc.z = fmaf(f0, v0.z, acc.z); acc.w = fmaf(f0, v0.w, acc.w);
            acc.x = fmaf(f1, v1.x, acc.x); acc.y = fmaf(f1, v1.y, acc.y);
            acc.z = fmaf(f1, v1.z, acc.z); acc.w = fmaf(f1, v1.w, acc.w);
            acc.x = fmaf(f2, v2.x, acc.x); acc.y = fmaf(f2, v2.y, acc.y);
            acc.z = fmaf(f2, v2.z, acc.z); acc.w = fmaf(f2, v2.w, acc.w);
            acc.x = fmaf(f3, v3.x, acc.x); acc.y = fmaf(f3, v3.y, acc.y);
            acc.z = fmaf(f3, v3.z, acc.z); acc.w = fmaf(f3, v3.w, acc.w);
            acc.x = fmaf(f4, v4.x, acc.x); acc.y = fmaf(f4, v4.y, acc.y);
            acc.z = fmaf(f4, v4.z, acc.z); acc.w = fmaf(f4, v4.w, acc.w);
            acc.x = fmaf(f5, v5.x, acc.x); acc.y = fmaf(f5, v5.y, acc.y);
            acc.z = fmaf(f5, v5.z, acc.z); acc.w = fmaf(f5, v5.w, acc.w);
            acc.x = fmaf(f6, v6.x, acc.x); acc.y = fmaf(f6, v6.y, acc.y);
            acc.z = fmaf(f6, v6.z, acc.z); acc.w = fmaf(f6, v6.w, acc.w);
            acc.x = fmaf(f7, v7.x, acc.x); acc.y = fmaf(f7, v7.y, acc.y);
            acc.z = fmaf(f7, v7.z, acc.z); acc.w = fmaf(f7, v7.w, acc.w);
        }
        for (; j < m; j++) {
            int2 e = sedge[wid][j];
            float4 v = ebs4[(size_t)e.x * 32 + lane];
            float f = __int_as_float(e.y);
            acc.x = fmaf(f, v.x, acc.x);
            acc.y = fmaf(f, v.y, acc.y);
            acc.z = fmaf(f, v.z, acc.z);
            acc.w = fmaf(f, v.w, acc.w);
        }
        __syncwarp();
    }
    reinterpret_cast<float4*>(g_li)[(size_t)row * 32 + lane] = acc;
}

// ---------------------------------------------------------------------------
// 5) Fused GEMM+ReLU (unchanged)
// ---------------------------------------------------------------------------
__global__ __launch_bounds__(256, 2)
void gemm_relu_kernel(const float* __restrict__ Wu,
                      const float* __restrict__ Wi,
                      float*       __restrict__ out) {
    __shared__ float As[2][8][128];
    __shared__ float Ws[2][8][128];

    int b = blockIdx.x;
    int entity = (b >= GEMM_BLOCKS_PER_ENT) ? 1 : 0;
    const float* W = entity ? Wi : Wu;
    int rowBase = (b - entity * GEMM_BLOCKS_PER_ENT) * 128;
    const float* A = g_li + (size_t)(entity ? N_USER : 0) * DIM;
    float* O = out + (size_t)(entity ? N_USER : 0) * DIM;

    int tid = threadIdx.x;
    int arow = tid >> 1;
    int akq  = (tid & 1) * 4;
    int agrow = rowBase + arow;
    bool avalid = (agrow < M_ENT);
    const float* aptr = A + (size_t)agrow * DIM + akq;
    int wk = tid >> 5;
    int wc = (tid & 31) * 4;
    const float* wptr = W + (size_t)wk * DIM + wc;

    int tx = tid & 15;
    int ty = tid >> 4;

    float acc[8][8];
#pragma unroll
    for (int i = 0; i < 8; i++)
#pragma unroll
        for (int j = 0; j < 8; j++) acc[i][j] = 0.f;

    {
        float4 a = avalid ? *reinterpret_cast<const float4*>(aptr)
                          : make_float4(0.f, 0.f, 0.f, 0.f);
        As[0][akq + 0][arow] = a.x;
        As[0][akq + 1][arow] = a.y;
        As[0][akq + 2][arow] = a.z;
        As[0][akq + 3][arow] = a.w;
        float4 w = *reinterpret_cast<const float4*>(wptr);
        *reinterpret_cast<float4*>(&Ws[0][wk][wc]) = w;
    }
    __syncthreads();

    int buf = 0;
#pragma unroll
    for (int t = 0; t < 16; t++) {
        if (t < 15) {
            int kk = (t + 1) * 8;
            float4 a = avalid ? *reinterpret_cast<const float4*>(aptr + kk)
                              : make_float4(0.f, 0.f, 0.f, 0.f);
            float4 w = *reinterpret_cast<const float4*>(wptr + (size_t)kk * DIM);
            int nb = buf ^ 1;
            As[nb][akq + 0][arow] = a.x;
            As[nb][akq + 1][arow] = a.y;
            As[nb][akq + 2][arow] = a.z;
            As[nb][akq + 3][arow] = a.w;
            *reinterpret_cast<float4*>(&Ws[nb][wk][wc]) = w;
        }

#pragma unroll
        for (int k = 0; k < 8; k++) {
            float4 a0 = *reinterpret_cast<const float4*>(&As[buf][k][ty * 8]);
            float4 a1 = *reinterpret_cast<const float4*>(&As[buf][k][ty * 8 + 4]);
            float4 w0 = *reinterpret_cast<const float4*>(&Ws[buf][k][tx * 8]);
            float4 w1 = *reinterpret_cast<const float4*>(&Ws[buf][k][tx * 8 + 4]);
            float av[8] = {a0.x, a0.y, a0.z, a0.w, a1.x, a1.y, a1.z, a1.w};
            float wv[8] = {w0.x, w0.y, w0.z, w0.w, w1.x, w1.y, w1.z, w1.w};
#pragma unroll
            for (int i = 0; i < 8; i++)
#pragma unroll
                for (int j = 0; j < 8; j++)
                    acc[i][j] = fmaf(av[i], wv[j], acc[i][j]);
        }
        __syncthreads();
        buf ^= 1;
    }

#pragma unroll
    for (int i = 0; i < 8; i++) {
        int row = rowBase + ty * 8 + i;
        if (row < M_ENT) {
            float4 o0, o1;
            o0.x = fmaxf(acc[i][0], 0.f);
            o0.y = fmaxf(acc[i][1], 0.f);
            o0.z = fmaxf(acc[i][2], 0.f);
            o0.w = fmaxf(acc[i][3], 0.f);
            o1.x = fmaxf(acc[i][4], 0.f);
            o1.y = fmaxf(acc[i][5], 0.f);
            o1.z = fmaxf(acc[i][6], 0.f);
            o1.w = fmaxf(acc[i][7], 0.f);
            *reinterpret_cast<float4*>(O + (size_t)row * DIM + tx * 8)     = o0;
            *reinterpret_cast<float4*>(O + (size_t)row * DIM + tx * 8 + 4) = o1;
        }
    }
}

// ---------------------------------------------------------------------------
extern "C" void kernel_launch(void* const* d_in, const int* in_sizes, int n_in,
                              void* d_out, int out_size) {
    const float* ebs    = (const float*)d_in[0];
    const int*   rows_u = (const int*)  d_in[1];
    const int*   cols_u = (const int*)  d_in[2];
    const float* vals_u = (const float*)d_in[3];
    const float* W_u    = (const float*)d_in[4];
    const int*   rows_i = (const int*)  d_in[5];
    const int*   cols_i = (const int*)  d_in[6];
    const float* vals_i = (const float*)d_in[7];
    const float* W_i    = (const float*)d_in[8];
    float* out = (float*)d_out;

    int E_u = in_sizes[1];
    int E_i = in_sizes[5];
    int E_total = E_u + E_i;

    zero_cnt_kernel<<<(N_TOTAL + 255) / 256, 256>>>();
    hist_kernel<<<(E_total + 255) / 256, 256>>>(rows_u, rows_i, E_u, E_i);
    scan_kernel<<<1, SCAN_THREADS>>>();
    permute_kernel<<<(E_total + 255) / 256, 256>>>(rows_u, cols_u, vals_u,
                                                   rows_i, cols_i, vals_i,
                                                   E_u, E_i);
    spmm_kernel<<<(N_TOTAL + 7) / 8, 256>>>(ebs);
    gemm_relu_kernel<<<2 * GEMM_BLOCKS_PER_ENT, 256>>>(W_u, W_i, out);
}

// round 5
// speedup vs baseline: 1.3641x; 1.3024x over previous
#include <cuda_runtime.h>
#include <cstdint>

#define N_TOTAL 100000
#define DIM     128
#define N_USER  50000
#define M_ENT   50000
#define GEMM_BLOCKS_PER_ENT 391   // ceil(50000/128)

// 51.2 MB scratch accumulator for LI_side_embed
__device__ float g_li[(size_t)N_TOTAL * DIM];

// ---------------------------------------------------------------------------
// packed-f32x2 helpers (Blackwell FFMA2 path; ptxas never auto-generates it)
// ---------------------------------------------------------------------------
__device__ __forceinline__ unsigned long long pk2(float x) {
    unsigned long long r;
    asm("mov.b64 %0, {%1, %1};" : "=l"(r) : "r"(__float_as_uint(x)));
    return r;
}
__device__ __forceinline__ void fma2(unsigned long long& d,
                                     unsigned long long a,
                                     unsigned long long b) {
    asm("fma.rn.f32x2 %0, %1, %2, %0;" : "+l"(d) : "l"(a), "l"(b));
}
__device__ __forceinline__ float2 up2(unsigned long long v) {
    float2 f;
    asm("mov.b64 {%0, %1}, %2;" : "=f"(f.x), "=f"(f.y) : "l"(v));
    return f;
}

// ---------------------------------------------------------------------------
// Zero the accumulator
// ---------------------------------------------------------------------------
__global__ void zero_li_kernel() {
    int i = blockIdx.x * blockDim.x + threadIdx.x;
    float4* p = reinterpret_cast<float4*>(g_li);
    const int n4 = (N_TOTAL * DIM) / 4;
    if (i < n4) p[i] = make_float4(0.f, 0.f, 0.f, 0.f);
}

// ---------------------------------------------------------------------------
// COO scatter, both entities in one launch: one warp per edge.
// li[row_offset + rows[e]] += vals[e] * ebs[cols[e]]   (vector f32x4 atomic)
// ---------------------------------------------------------------------------
__global__ void scatter_kernel(const int*   __restrict__ rows_u,
                               const int*   __restrict__ cols_u,
                               const float* __restrict__ vals_u,
                               const int*   __restrict__ rows_i,
                               const int*   __restrict__ cols_i,
                               const float* __restrict__ vals_i,
                               const float* __restrict__ ebs,
                               int E_u, int E_i) {
    int gwid = (blockIdx.x * blockDim.x + threadIdx.x) >> 5;
    int lane = threadIdx.x & 31;

    const int* rows; const int* cols; const float* vals;
    int row_offset, e;
    if (gwid < E_u) {
        rows = rows_u; cols = cols_u; vals = vals_u; row_offset = 0; e = gwid;
    } else {
        e = gwid - E_u;
        if (e >= E_i) return;
        rows = rows_i; cols = cols_i; vals = vals_i; row_offset = N_USER;
    }

    int   r = __ldg(rows + e);
    int   c = __ldg(cols + e);
    float v = __ldg(vals + e);

    const float4* src = reinterpret_cast<const float4*>(ebs + (size_t)c * DIM);
    float4 ev = src[lane];
    float4 m = make_float4(ev.x * v, ev.y * v, ev.z * v, ev.w * v);

    float4* dst = reinterpret_cast<float4*>(g_li + (size_t)(row_offset + r) * DIM);
    atomicAdd(dst + lane, m);
}

// ---------------------------------------------------------------------------
// Fused GEMM+ReLU for both entities, one launch, FFMA2 inner loop.
// BM=128, BN=128, BK=8, 256 threads, 8x8 tile per thread (as 8x4 f32x2 pairs).
// ---------------------------------------------------------------------------
__global__ __launch_bounds__(256, 2)
void gemm_relu_kernel(const float* __restrict__ Wu,
                      const float* __restrict__ Wi,
                      float*       __restrict__ out) {
    __shared__ float As[2][8][128];   // [buf][k][row]
    __shared__ float Ws[2][8][128];   // [buf][k][col]

    int b = blockIdx.x;
    int entity = (b >= GEMM_BLOCKS_PER_ENT) ? 1 : 0;
    const float* W = entity ? Wi : Wu;
    int rowBase = (b - entity * GEMM_BLOCKS_PER_ENT) * 128;
    const float* A = g_li + (size_t)(entity ? N_USER : 0) * DIM;
    float* O = out + (size_t)(entity ? N_USER : 0) * DIM;

    int tid = threadIdx.x;
    int arow = tid >> 1;
    int akq  = (tid & 1) * 4;
    int agrow = rowBase + arow;
    bool avalid = (agrow < M_ENT);
    const float* aptr = A + (size_t)agrow * DIM + akq;
    int wk = tid >> 5;
    int wc = (tid & 31) * 4;
    const float* wptr = W + (size_t)wk * DIM + wc;

    int tx = tid & 15;   // cols tx*8..tx*8+7
    int ty = tid >> 4;   // rows ty*8..ty*8+7

    // accumulators: 8 rows x 4 packed f32x2 pairs (= 8x8 floats)
    unsigned long long acc2[8][4];
#pragma unroll
    for (int i = 0; i < 8; i++)
#pragma unroll
        for (int j = 0; j < 4; j++) acc2[i][j] = 0ULL;

    // first tile -> buf 0
    {
        float4 a = avalid ? *reinterpret_cast<const float4*>(aptr)
                          : make_float4(0.f, 0.f, 0.f, 0.f);
        As[0][akq + 0][arow] = a.x;
        As[0][akq + 1][arow] = a.y;
        As[0][akq + 2][arow] = a.z;
        As[0][akq + 3][arow] = a.w;
        float4 w = *reinterpret_cast<const float4*>(wptr);
        *reinterpret_cast<float4*>(&Ws[0][wk][wc]) = w;
    }
    __syncthreads();

    int buf = 0;
#pragma unroll
    for (int t = 0; t < 16; t++) {
        if (t < 15) {
            int kk = (t + 1) * 8;
            float4 a = avalid ? *reinterpret_cast<const float4*>(aptr + kk)
                              : make_float4(0.f, 0.f, 0.f, 0.f);
            float4 w = *reinterpret_cast<const float4*>(wptr + (size_t)kk * DIM);
            int nb = buf ^ 1;
            As[nb][akq + 0][arow] = a.x;
            As[nb][akq + 1][arow] = a.y;
            As[nb][akq + 2][arow] = a.z;
            As[nb][akq + 3][arow] = a.w;
            *reinterpret_cast<float4*>(&Ws[nb][wk][wc]) = w;
        }

#pragma unroll
        for (int k = 0; k < 8; k++) {
            float4 a0 = *reinterpret_cast<const float4*>(&As[buf][k][ty * 8]);
            float4 a1 = *reinterpret_cast<const float4*>(&As[buf][k][ty * 8 + 4]);
            // W pairs are contiguous in smem -> load directly as packed 64-bit
            ulonglong2 wq0 = *reinterpret_cast<const ulonglong2*>(&Ws[buf][k][tx * 8]);
            ulonglong2 wq1 = *reinterpret_cast<const ulonglong2*>(&Ws[buf][k][tx * 8 + 4]);
            unsigned long long wv2[4] = {wq0.x, wq0.y, wq1.x, wq1.y};
            float av[8] = {a0.x, a0.y, a0.z, a0.w, a1.x, a1.y, a1.z, a1.w};
#pragma unroll
            for (int i = 0; i < 8; i++) {
                unsigned long long ad = pk2(av[i]);
#pragma unroll
                for (int j = 0; j < 4; j++)
                    fma2(acc2[i][j], ad, wv2[j]);
            }
        }
        __syncthreads();
        buf ^= 1;
    }

    // epilogue: unpack, ReLU, store
#pragma unroll
    for (int i = 0; i < 8; i++) {
        int row = rowBase + ty * 8 + i;
        if (row < M_ENT) {
            float2 p0 = up2(acc2[i][0]);
            float2 p1 = up2(acc2[i][1]);
            float2 p2 = up2(acc2[i][2]);
            float2 p3 = up2(acc2[i][3]);
            float4 o0, o1;
            o0.x = fmaxf(p0.x, 0.f); o0.y = fmaxf(p0.y, 0.f);
            o0.z = fmaxf(p1.x, 0.f); o0.w = fmaxf(p1.y, 0.f);
            o1.x = fmaxf(p2.x, 0.f); o1.y = fmaxf(p2.y, 0.f);
            o1.z = fmaxf(p3.x, 0.f); o1.w = fmaxf(p3.y, 0.f);
            *reinterpret_cast<float4*>(O + (size_t)row * DIM + tx * 8)     = o0;
            *reinterpret_cast<float4*>(O + (size_t)row * DIM + tx * 8 + 4) = o1;
        }
    }
}

// ---------------------------------------------------------------------------
extern "C" void kernel_launch(void* const* d_in, const int* in_sizes, int n_in,
                              void* d_out, int out_size) {
    const float* ebs    = (const float*)d_in[0];
    const int*   rows_u = (const int*)  d_in[1];
    const int*   cols_u = (const int*)  d_in[2];
    const float* vals_u = (const float*)d_in[3];
    const float* W_u    = (const float*)d_in[4];
    const int*   rows_i = (const int*)  d_in[5];
    const int*   cols_i = (const int*)  d_in[6];
    const float* vals_i = (const float*)d_in[7];
    const float* W_i    = (const float*)d_in[8];
    float* out = (float*)d_out;

    int E_u = in_sizes[1];
    int E_i = in_sizes[5];

    // 1) zero accumulator
    {
        int n4 = (N_TOTAL * DIM) / 4;
        zero_li_kernel<<<(n4 + 255) / 256, 256>>>();
    }

    // 2) fused scatter (one warp per edge)
    {
        int total_warps = E_u + E_i;
        int blocks = (total_warps + 7) / 8;
        scatter_kernel<<<blocks, 256>>>(rows_u, cols_u, vals_u,
                                        rows_i, cols_i, vals_i,
                                        ebs, E_u, E_i);
    }

    // 3) fused GEMM + ReLU (FFMA2)
    gemm_relu_kernel<<<2 * GEMM_BLOCKS_PER_ENT, 256>>>(W_u, W_i, out);
}

// round 6
// speedup vs baseline: 1.3951x; 1.0227x over previous
#include <cuda_runtime.h>
#include <cstdint>

#define N_TOTAL 100000
#define DIM     128
#define N_USER  50000
#define M_ENT   50000
#define GEMM_BLOCKS_PER_ENT 391   // ceil(50000/128)

// 51.2 MB scratch accumulator for LI_side_embed
__device__ float g_li[(size_t)N_TOTAL * DIM];

// ---------------------------------------------------------------------------
// Zero the accumulator
// ---------------------------------------------------------------------------
__global__ void zero_li_kernel() {
    int i = blockIdx.x * blockDim.x + threadIdx.x;
    float4* p = reinterpret_cast<float4*>(g_li);
    const int n4 = (N_TOTAL * DIM) / 4;
    if (i < n4) p[i] = make_float4(0.f, 0.f, 0.f, 0.f);
}

// ---------------------------------------------------------------------------
// COO scatter, both entities in one launch: one warp per edge.
// li[row_offset + rows[e]] += vals[e] * ebs[cols[e]]   (vector f32x4 atomic)
// ---------------------------------------------------------------------------
__global__ void scatter_kernel(const int*   __restrict__ rows_u,
                               const int*   __restrict__ cols_u,
                               const float* __restrict__ vals_u,
                               const int*   __restrict__ rows_i,
                               const int*   __restrict__ cols_i,
                               const float* __restrict__ vals_i,
                               const float* __restrict__ ebs,
                               int E_u, int E_i) {
    int gwid = (blockIdx.x * blockDim.x + threadIdx.x) >> 5;
    int lane = threadIdx.x & 31;

    const int* rows; const int* cols; const float* vals;
    int row_offset, e;
    if (gwid < E_u) {
        rows = rows_u; cols = cols_u; vals = vals_u; row_offset = 0; e = gwid;
    } else {
        e = gwid - E_u;
        if (e >= E_i) return;
        rows = rows_i; cols = cols_i; vals = vals_i; row_offset = N_USER;
    }

    int   r = __ldg(rows + e);
    int   c = __ldg(cols + e);
    float v = __ldg(vals + e);

    const float4* src = reinterpret_cast<const float4*>(ebs + (size_t)c * DIM);
    float4 ev = src[lane];
    float4 m = make_float4(ev.x * v, ev.y * v, ev.z * v, ev.w * v);

    float4* dst = reinterpret_cast<float4*>(g_li + (size_t)(row_offset + r) * DIM);
    atomicAdd(dst + lane, m);
}

// ---------------------------------------------------------------------------
// TF32 tensor-core GEMM + ReLU.
// Grid: 2*391 blocks, 256 threads (8 warps). Block tile = 128 rows x 128 cols.
// Each warp: 16 rows x 128 cols via mma.sync.m16n8k8 (16 n-tiles, 16 k-steps).
// No smem, no __syncthreads: A from L2-resident g_li, W from L1 (64KB, hot).
// ---------------------------------------------------------------------------
__device__ __forceinline__ unsigned cvt_tf32(float f) {
    unsigned r;
    asm("cvt.rna.tf32.f32 %0, %1;" : "=r"(r) : "f"(f));
    return r;
}

__global__ __launch_bounds__(256)
void gemm_relu_tf32_kernel(const float* __restrict__ Wu,
                           const float* __restrict__ Wi,
                           float*       __restrict__ out) {
    int b = blockIdx.x;
    int entity = (b >= GEMM_BLOCKS_PER_ENT) ? 1 : 0;
    const float* W = entity ? Wi : Wu;
    int blockRow = (b - entity * GEMM_BLOCKS_PER_ENT) * 128;
    const float* A = g_li + (size_t)(entity ? N_USER : 0) * DIM;
    float* O = out + (size_t)(entity ? N_USER : 0) * DIM;

    int warp = threadIdx.x >> 5;
    int lane = threadIdx.x & 31;
    int lq = lane >> 2;          // 0..7  (group id)
    int lr = lane & 3;           // 0..3  (id in group)

    int rbase = blockRow + warp * 16;
    int row_a  = rbase + lq;          // fragment rows lq and lq+8
    int row_a2 = row_a + 8;
    bool va  = row_a  < M_ENT;
    bool va2 = row_a2 < M_ENT;
    const float* pa  = A + (size_t)(va  ? row_a  : 0) * DIM + lr;
    const float* pa2 = A + (size_t)(va2 ? row_a2 : 0) * DIM + lr;
    // B fragment base: b0 at W[k0+lr][n*8+lq], b1 at W[k0+4+lr][n*8+lq]
    const float* pb = W + (size_t)lr * DIM + lq;

    float acc[16][4];
#pragma unroll
    for (int n = 0; n < 16; n++)
#pragma unroll
        for (int j = 0; j < 4; j++) acc[n][j] = 0.f;

#pragma unroll 1
    for (int ks = 0; ks < 16; ks++) {
        int k0 = ks * 8;
        // A fragment (reused across all 16 n-tiles)
        unsigned a0 = cvt_tf32(__ldg(pa  + k0));
        unsigned a1 = cvt_tf32(__ldg(pa2 + k0));
        unsigned a2 = cvt_tf32(__ldg(pa  + k0 + 4));
        unsigned a3 = cvt_tf32(__ldg(pa2 + k0 + 4));

        const float* pbk = pb + (size_t)k0 * DIM;
#pragma unroll
        for (int n = 0; n < 16; n++) {
            unsigned b0 = cvt_tf32(__ldg(pbk + n * 8));
            unsigned b1 = cvt_tf32(__ldg(pbk + 4 * DIM + n * 8));
            asm volatile(
                "mma.sync.aligned.m16n8k8.row.col.f32.tf32.tf32.f32 "
                "{%0,%1,%2,%3}, {%4,%5,%6,%7}, {%8,%9}, {%0,%1,%2,%3};\n"
                : "+f"(acc[n][0]), "+f"(acc[n][1]), "+f"(acc[n][2]), "+f"(acc[n][3])
                : "r"(a0), "r"(a1), "r"(a2), "r"(a3), "r"(b0), "r"(b1));
        }
    }

    // epilogue: ReLU + float2 stores
    // c0: (row_a,  col), c1: (row_a,  col+1), c2: (row_a2, col), c3: (row_a2, col+1)
#pragma unroll
    for (int n = 0; n < 16; n++) {
        int col = n * 8 + lr * 2;
        if (va) {
            float2 o;
            o.x = fmaxf(acc[n][0], 0.f);
            o.y = fmaxf(acc[n][1], 0.f);
            *reinterpret_cast<float2*>(O + (size_t)row_a * DIM + col) = o;
        }
        if (va2) {
            float2 o;
            o.x = fmaxf(acc[n][2], 0.f);
            o.y = fmaxf(acc[n][3], 0.f);
            *reinterpret_cast<float2*>(O + (size_t)row_a2 * DIM + col) = o;
        }
    }
}

// ---------------------------------------------------------------------------
extern "C" void kernel_launch(void* const* d_in, const int* in_sizes, int n_in,
                              void* d_out, int out_size) {
    const float* ebs    = (const float*)d_in[0];
    const int*   rows_u = (const int*)  d_in[1];
    const int*   cols_u = (const int*)  d_in[2];
    const float* vals_u = (const float*)d_in[3];
    const float* W_u    = (const float*)d_in[4];
    const int*   rows_i = (const int*)  d_in[5];
    const int*   cols_i = (const int*)  d_in[6];
    const float* vals_i = (const float*)d_in[7];
    const float* W_i    = (const float*)d_in[8];
    float* out = (float*)d_out;

    int E_u = in_sizes[1];
    int E_i = in_sizes[5];

    // 1) zero accumulator
    {
        int n4 = (N_TOTAL * DIM) / 4;
        zero_li_kernel<<<(n4 + 255) / 256, 256>>>();
    }

    // 2) fused scatter (one warp per edge)
    {
        int total_warps = E_u + E_i;
        int blocks = (total_warps + 7) / 8;
        scatter_kernel<<<blocks, 256>>>(rows_u, cols_u, vals_u,
                                        rows_i, cols_i, vals_i,
                                        ebs, E_u, E_i);
    }

    // 3) TF32 tensor-core GEMM + ReLU
    gemm_relu_tf32_kernel<<<2 * GEMM_BLOCKS_PER_ENT, 256>>>(W_u, W_i, out);
}

// round 7
// speedup vs baseline: 1.5692x; 1.1248x over previous
#include <cuda_runtime.h>
#include <cstdint>

#define N_TOTAL 100000
#define DIM     128
#define N_USER  50000
#define M_ENT   50000
#define GEMM_BLOCKS_PER_ENT 391   // ceil(50000/128)

// 51.2 MB scratch accumulator for LI_side_embed
__device__ float g_li[(size_t)N_TOTAL * DIM];
// W matrices pre-converted to TF32 (u32 bit patterns), dense [k][n]
__device__ unsigned g_wt[2][DIM * DIM];

__device__ __forceinline__ unsigned cvt_tf32(float f) {
    unsigned r;
    asm("cvt.rna.tf32.f32 %0, %1;" : "=r"(r) : "f"(f));
    return r;
}

// ---------------------------------------------------------------------------
// Zero the accumulator
// ---------------------------------------------------------------------------
__global__ void zero_li_kernel() {
    int i = blockIdx.x * blockDim.x + threadIdx.x;
    float4* p = reinterpret_cast<float4*>(g_li);
    const int n4 = (N_TOTAL * DIM) / 4;
    if (i < n4) p[i] = make_float4(0.f, 0.f, 0.f, 0.f);
}

// ---------------------------------------------------------------------------
// COO scatter, both entities in one launch: one warp per edge.
// ---------------------------------------------------------------------------
__global__ void scatter_kernel(const int*   __restrict__ rows_u,
                               const int*   __restrict__ cols_u,
                               const float* __restrict__ vals_u,
                               const int*   __restrict__ rows_i,
                               const int*   __restrict__ cols_i,
                               const float* __restrict__ vals_i,
                               const float* __restrict__ ebs,
                               int E_u, int E_i) {
    int gwid = (blockIdx.x * blockDim.x + threadIdx.x) >> 5;
    int lane = threadIdx.x & 31;

    const int* rows; const int* cols; const float* vals;
    int row_offset, e;
    if (gwid < E_u) {
        rows = rows_u; cols = cols_u; vals = vals_u; row_offset = 0; e = gwid;
    } else {
        e = gwid - E_u;
        if (e >= E_i) return;
        rows = rows_i; cols = cols_i; vals = vals_i; row_offset = N_USER;
    }

    int   r = __ldg(rows + e);
    int   c = __ldg(cols + e);
    float v = __ldg(vals + e);

    const float4* src = reinterpret_cast<const float4*>(ebs + (size_t)c * DIM);
    float4 ev = src[lane];
    float4 m = make_float4(ev.x * v, ev.y * v, ev.z * v, ev.w * v);

    float4* dst = reinterpret_cast<float4*>(g_li + (size_t)(row_offset + r) * DIM);
    atomicAdd(dst + lane, m);
}

// ---------------------------------------------------------------------------
// Convert W_u, W_i to TF32 once. 2*16384 elements.
// ---------------------------------------------------------------------------
__global__ void wconv_kernel(const float* __restrict__ Wu,
                             const float* __restrict__ Wi) {
    int i = blockIdx.x * blockDim.x + threadIdx.x;
    if (i < DIM * DIM) {
        g_wt[0][i] = cvt_tf32(__ldg(Wu + i));
        g_wt[1][i] = cvt_tf32(__ldg(Wi + i));
    }
}

// ---------------------------------------------------------------------------
// TF32 tensor-core GEMM + ReLU, W staged in smem (padded, conflict-free).
// Block = 128 rows x 128 cols, 8 warps, each warp 16 rows x 128 cols.
// B fragments from smem (no cvt in loop); A fragments direct LDG (L2-hot).
// ---------------------------------------------------------------------------
__global__ __launch_bounds__(256)
void gemm_relu_tf32_kernel(float* __restrict__ out) {
    __shared__ unsigned Ws[DIM][132];   // padded row stride -> conflict-free frag loads

    int b = blockIdx.x;
    int entity = (b >= GEMM_BLOCKS_PER_ENT) ? 1 : 0;
    int blockRow = (b - entity * GEMM_BLOCKS_PER_ENT) * 128;
    const float* A = g_li + (size_t)(entity ? N_USER : 0) * DIM;
    float* O = out + (size_t)(entity ? N_USER : 0) * DIM;

    // stage W (tf32) into smem, coalesced
    {
        const unsigned* src = g_wt[entity];
        int tid = threadIdx.x;
#pragma unroll
        for (int i = 0; i < (DIM * DIM) / 256; i++) {
            int idx = tid + i * 256;
            Ws[idx >> 7][idx & 127] = src[idx];
        }
    }
    __syncthreads();

    int warp = threadIdx.x >> 5;
    int lane = threadIdx.x & 31;
    int lq = lane >> 2;          // 0..7
    int lr = lane & 3;           // 0..3

    int rbase = blockRow + warp * 16;
    int row_a  = rbase + lq;
    int row_a2 = row_a + 8;
    bool va  = row_a  < M_ENT;
    bool va2 = row_a2 < M_ENT;
    const float* pa  = A + (size_t)(va  ? row_a  : 0) * DIM + lr;
    const float* pa2 = A + (size_t)(va2 ? row_a2 : 0) * DIM + lr;

    float acc[16][4];
#pragma unroll
    for (int n = 0; n < 16; n++)
#pragma unroll
        for (int j = 0; j < 4; j++) acc[n][j] = 0.f;

#pragma unroll 2
    for (int ks = 0; ks < 16; ks++) {
        int k0 = ks * 8;
        unsigned a0 = cvt_tf32(__ldg(pa  + k0));
        unsigned a1 = cvt_tf32(__ldg(pa2 + k0));
        unsigned a2 = cvt_tf32(__ldg(pa  + k0 + 4));
        unsigned a3 = cvt_tf32(__ldg(pa2 + k0 + 4));

        const unsigned* wr0 = &Ws[k0 + lr][lq];
        const unsigned* wr1 = &Ws[k0 + 4 + lr][lq];
#pragma unroll
        for (int n = 0; n < 16; n++) {
            unsigned b0 = wr0[n * 8];
            unsigned b1 = wr1[n * 8];
            asm volatile(
                "mma.sync.aligned.m16n8k8.row.col.f32.tf32.tf32.f32 "
                "{%0,%1,%2,%3}, {%4,%5,%6,%7}, {%8,%9}, {%0,%1,%2,%3};\n"
                : "+f"(acc[n][0]), "+f"(acc[n][1]), "+f"(acc[n][2]), "+f"(acc[n][3])
                : "r"(a0), "r"(a1), "r"(a2), "r"(a3), "r"(b0), "r"(b1));
        }
    }

    // epilogue: ReLU + float2 stores
#pragma unroll
    for (int n = 0; n < 16; n++) {
        int col = n * 8 + lr * 2;
        if (va) {
            float2 o;
            o.x = fmaxf(acc[n][0], 0.f);
            o.y = fmaxf(acc[n][1], 0.f);
            *reinterpret_cast<float2*>(O + (size_t)row_a * DIM + col) = o;
        }
        if (va2) {
            float2 o;
            o.x = fmaxf(acc[n][2], 0.f);
            o.y = fmaxf(acc[n][3], 0.f);
            *reinterpret_cast<float2*>(O + (size_t)row_a2 * DIM + col) = o;
        }
    }
}

// ---------------------------------------------------------------------------
extern "C" void kernel_launch(void* const* d_in, const int* in_sizes, int n_in,
                              void* d_out, int out_size) {
    const float* ebs    = (const float*)d_in[0];
    const int*   rows_u = (const int*)  d_in[1];
    const int*   cols_u = (const int*)  d_in[2];
    const float* vals_u = (const float*)d_in[3];
    const float* W_u    = (const float*)d_in[4];
    const int*   rows_i = (const int*)  d_in[5];
    const int*   cols_i = (const int*)  d_in[6];
    const float* vals_i = (const float*)d_in[7];
    const float* W_i    = (const float*)d_in[8];
    float* out = (float*)d_out;

    int E_u = in_sizes[1];
    int E_i = in_sizes[5];

    // 1) zero accumulator
    {
        int n4 = (N_TOTAL * DIM) / 4;
        zero_li_kernel<<<(n4 + 255) / 256, 256>>>();
    }

    // 2) fused scatter (one warp per edge)
    {
        int total_warps = E_u + E_i;
        int blocks = (total_warps + 7) / 8;
        scatter_kernel<<<blocks, 256>>>(rows_u, cols_u, vals_u,
                                        rows_i, cols_i, vals_i,
                                        ebs, E_u, E_i);
    }

    // 3) convert W to TF32 (also positions GEMM as launch #4 for ncu)
    wconv_kernel<<<(DIM * DIM + 255) / 256, 256>>>(W_u, W_i);

    // 4) TF32 tensor-core GEMM + ReLU (smem-staged W)
    gemm_relu_tf32_kernel<<<2 * GEMM_BLOCKS_PER_ENT, 256>>>(out);
}

// round 8
// speedup vs baseline: 1.6470x; 1.0496x over previous
#include <cuda_runtime.h>
#include <cstdint>

#define N_TOTAL 100000
#define DIM     128
#define N_USER  50000
#define M_ENT   50000
#define GEMM_BLOCKS_PER_ENT 391   // ceil(50000/128)

// 51.2 MB scratch accumulator for LI_side_embed
__device__ float g_li[(size_t)N_TOTAL * DIM];
// W matrices pre-converted to TF32, fragment-permuted layout: [k][lq*16 + n]
// where original col = n*8 + lq  (lq = 0..7, n = 0..15)
__device__ unsigned g_wt[2][DIM * DIM];

__device__ __forceinline__ unsigned cvt_tf32(float f) {
    unsigned r;
    asm("cvt.rna.tf32.f32 %0, %1;" : "=r"(r) : "f"(f));
    return r;
}

// ---------------------------------------------------------------------------
// Zero the accumulator
// ---------------------------------------------------------------------------
__global__ void zero_li_kernel() {
    int i = blockIdx.x * blockDim.x + threadIdx.x;
    float4* p = reinterpret_cast<float4*>(g_li);
    const int n4 = (N_TOTAL * DIM) / 4;
    if (i < n4) p[i] = make_float4(0.f, 0.f, 0.f, 0.f);
}

// ---------------------------------------------------------------------------
// COO scatter, both entities in one launch: one warp per edge.
// ---------------------------------------------------------------------------
__global__ void scatter_kernel(const int*   __restrict__ rows_u,
                               const int*   __restrict__ cols_u,
                               const float* __restrict__ vals_u,
                               const int*   __restrict__ rows_i,
                               const int*   __restrict__ cols_i,
                               const float* __restrict__ vals_i,
                               const float* __restrict__ ebs,
                               int E_u, int E_i) {
    int gwid = (blockIdx.x * blockDim.x + threadIdx.x) >> 5;
    int lane = threadIdx.x & 31;

    const int* rows; const int* cols; const float* vals;
    int row_offset, e;
    if (gwid < E_u) {
        rows = rows_u; cols = cols_u; vals = vals_u; row_offset = 0; e = gwid;
    } else {
        e = gwid - E_u;
        if (e >= E_i) return;
        rows = rows_i; cols = cols_i; vals = vals_i; row_offset = N_USER;
    }

    int   r = __ldg(rows + e);
    int   c = __ldg(cols + e);
    float v = __ldg(vals + e);

    const float4* src = reinterpret_cast<const float4*>(ebs + (size_t)c * DIM);
    float4 ev = src[lane];
    float4 m = make_float4(ev.x * v, ev.y * v, ev.z * v, ev.w * v);

    float4* dst = reinterpret_cast<float4*>(g_li + (size_t)(row_offset + r) * DIM);
    atomicAdd(dst + lane, m);
}

// ---------------------------------------------------------------------------
// Convert W to TF32 in fragment-permuted layout: g_wt[e][k*128 + lq*16 + n]
// = tf32(W[k][n*8 + lq]).
// ---------------------------------------------------------------------------
__global__ void wconv_kernel(const float* __restrict__ Wu,
                             const float* __restrict__ Wi) {
    int i = blockIdx.x * blockDim.x + threadIdx.x;
    if (i < DIM * DIM) {
        int k = i >> 7, c = i & 127;
        int lq = c >> 4, n = c & 15;
        int src = k * DIM + n * 8 + lq;
        g_wt[0][i] = cvt_tf32(__ldg(Wu + src));
        g_wt[1][i] = cvt_tf32(__ldg(Wi + src));
    }
}

// ---------------------------------------------------------------------------
// TF32 tensor-core GEMM + ReLU.
//  - W in smem, permuted layout, stride 132 (132 % 32 == 4 -> LDS.128 conflict-free)
//  - A staged through double-buffered smem (stride 12 -> conflict-free scalar LDS)
// Block = 128 rows x 128 cols, 8 warps, each warp 16 rows x all 128 cols.
// ---------------------------------------------------------------------------
__global__ __launch_bounds__(256, 2)
void gemm_relu_tf32_kernel(float* __restrict__ out) {
    __shared__ unsigned Ws[DIM][132];   // permuted W (tf32 bits)
    __shared__ float    As[2][DIM][12]; // A stage: [buf][row][k-in-stage], stride 12

    int b = blockIdx.x;
    int entity = (b >= GEMM_BLOCKS_PER_ENT) ? 1 : 0;
    int blockRow = (b - entity * GEMM_BLOCKS_PER_ENT) * 128;
    const float* A = g_li + (size_t)(entity ? N_USER : 0) * DIM;
    float* O = out + (size_t)(entity ? N_USER : 0) * DIM;

    int tid = threadIdx.x;

    // ---- stage W into smem (uint4 coalesced) ----
    {
        const uint4* s4 = reinterpret_cast<const uint4*>(g_wt[entity]);
#pragma unroll
        for (int i = 0; i < 16; i++) {
            int u = tid + i * 256;          // uint4 index, 4096 total
            uint4 v = s4[u];
            int idx = u * 4;
            *reinterpret_cast<uint4*>(&Ws[idx >> 7][idx & 127]) = v;
        }
    }

    // ---- A staging setup: one float4 per thread per k-stage ----
    int arow = tid >> 1;                 // 0..127 block-local row
    int acg  = tid & 1;                  // float4 index within 8-col stage
    int agrow = blockRow + arow;
    bool avalid = (agrow < M_ENT);
    const float* aptr = A + (size_t)(avalid ? agrow : 0) * DIM + acg * 4;

    // preload stage 0
    {
        float4 f = avalid ? *reinterpret_cast<const float4*>(aptr)
                          : make_float4(0.f, 0.f, 0.f, 0.f);
        *reinterpret_cast<float4*>(&As[0][arow][acg * 4]) = f;
    }
    __syncthreads();

    int warp = tid >> 5;
    int lane = tid & 31;
    int lq = lane >> 2;                  // 0..7
    int lr = lane & 3;                   // 0..3

    int rloc  = warp * 16 + lq;          // block-local fragment rows
    int rloc2 = rloc + 8;
    int row_a  = blockRow + rloc;
    int row_a2 = blockRow + rloc2;
    bool va  = row_a  < M_ENT;
    bool va2 = row_a2 < M_ENT;

    float acc[16][4];
#pragma unroll
    for (int n = 0; n < 16; n++)
#pragma unroll
        for (int j = 0; j < 4; j++) acc[n][j] = 0.f;

#pragma unroll 1
    for (int ks = 0; ks < 16; ks++) {
        int buf = ks & 1;

        // prefetch next A stage into registers
        float4 pf = make_float4(0.f, 0.f, 0.f, 0.f);
        if (ks < 15 && avalid)
            pf = *reinterpret_cast<const float4*>(aptr + (ks + 1) * 8);

        // B fragments: 8 x LDS.128, conflict-free
        uint4 b0q[4], b1q[4];
        {
            const uint4* w0 = reinterpret_cast<const uint4*>(&Ws[ks * 8 + lr][lq * 16]);
            const uint4* w1 = reinterpret_cast<const uint4*>(&Ws[ks * 8 + 4 + lr][lq * 16]);
#pragma unroll
            for (int j = 0; j < 4; j++) { b0q[j] = w0[j]; b1q[j] = w1[j]; }
        }
        const unsigned* bw0 = reinterpret_cast<const unsigned*>(b0q);
        const unsigned* bw1 = reinterpret_cast<const unsigned*>(b1q);

        // A fragments: 4 scalar LDS (stride-12 layout, conflict-free) + cvt
        unsigned a0 = cvt_tf32(As[buf][rloc ][lr    ]);
        unsigned a1 = cvt_tf32(As[buf][rloc2][lr    ]);
        unsigned a2 = cvt_tf32(As[buf][rloc ][lr + 4]);
        unsigned a3 = cvt_tf32(As[buf][rloc2][lr + 4]);

#pragma unroll
        for (int n = 0; n < 16; n++) {
            asm volatile(
                "mma.sync.aligned.m16n8k8.row.col.f32.tf32.tf32.f32 "
                "{%0,%1,%2,%3}, {%4,%5,%6,%7}, {%8,%9}, {%0,%1,%2,%3};\n"
                : "+f"(acc[n][0]), "+f"(acc[n][1]), "+f"(acc[n][2]), "+f"(acc[n][3])
                : "r"(a0), "r"(a1), "r"(a2), "r"(a3), "r"(bw0[n]), "r"(bw1[n]));
        }

        if (ks < 15)
            *reinterpret_cast<float4*>(&As[buf ^ 1][arow][acg * 4]) = pf;
        __syncthreads();
    }

    // epilogue: ReLU + float2 stores
#pragma unroll
    for (int n = 0; n < 16; n++) {
        int col = n * 8 + lr * 2;
        if (va) {
            float2 o;
            o.x = fmaxf(acc[n][0], 0.f);
            o.y = fmaxf(acc[n][1], 0.f);
            *reinterpret_cast<float2*>(O + (size_t)row_a * DIM + col) = o;
        }
        if (va2) {
            float2 o;
            o.x = fmaxf(acc[n][2], 0.f);
            o.y = fmaxf(acc[n][3], 0.f);
            *reinterpret_cast<float2*>(O + (size_t)row_a2 * DIM + col) = o;
        }
    }
}

// ---------------------------------------------------------------------------
extern "C" void kernel_launch(void* const* d_in, const int* in_sizes, int n_in,
                              void* d_out, int out_size) {
    const float* ebs    = (const float*)d_in[0];
    const int*   rows_u = (const int*)  d_in[1];
    const int*   cols_u = (const int*)  d_in[2];
    const float* vals_u = (const float*)d_in[3];
    const float* W_u    = (const float*)d_in[4];
    const int*   rows_i = (const int*)  d_in[5];
    const int*   cols_i = (const int*)  d_in[6];
    const float* vals_i = (const float*)d_in[7];
    const float* W_i    = (const float*)d_in[8];
    float* out = (float*)d_out;

    int E_u = in_sizes[1];
    int E_i = in_sizes[5];

    // 1) zero accumulator
    {
        int n4 = (N_TOTAL * DIM) / 4;
        zero_li_kernel<<<(n4 + 255) / 256, 256>>>();
    }

    // 2) fused scatter (one warp per edge)
    {
        int total_warps = E_u + E_i;
        int blocks = (total_warps + 7) / 8;
        scatter_kernel<<<blocks, 256>>>(rows_u, cols_u, vals_u,
                                        rows_i, cols_i, vals_i,
                                        ebs, E_u, E_i);
    }

    // 3) convert W to TF32 (permuted fragment layout)
    wconv_kernel<<<(DIM * DIM + 255) / 256, 256>>>(W_u, W_i);

    // 4) TF32 tensor-core GEMM + ReLU
    gemm_relu_tf32_kernel<<<2 * GEMM_BLOCKS_PER_ENT, 256>>>(out);
}